// round 16
// baseline (speedup 1.0000x reference)
#include <cuda_runtime.h>

#define B_ 8192
#define S_ 4096
#define TPB 256
#define CHUNK 16           // S_ / TPB
#define EPS_ 1e-8f
#define LNEPS_ 1e-5f

#define RPB 4
#define GRID_ (B_ / RPB)   // 2048 blocks

// ---------------------------------------------------------------------------
// Fused kernel: per block, feat for 4 rows (streaming, memory-bound) then
// MLP for the same 4 rows (compute-bound). Adjacent CTAs interleave phases,
// hiding MLP compute under the DRAM stream.
// ---------------------------------------------------------------------------
__global__ void __launch_bounds__(TPB) fused_kernel(
    const float* __restrict__ prices,
    const float* __restrict__ enc_w,  const float* __restrict__ enc_b,
    const float* __restrict__ enc_g,  const float* __restrict__ enc_beta,
    const float* __restrict__ W1,     const float* __restrict__ b1,
    const float* __restrict__ W2,     const float* __restrict__ b2,
    float* __restrict__ rf_out, float* __restrict__ probs_out)
{
    __shared__ float  s_rf[RPB][256];      // layernormed features
    __shared__ float  s_part[RPB][256];    // GEMM1 quarter partials
    __shared__ float  s_h[RPB][65];        // hidden (stride 65: conflict-free)
    __shared__ float  s_sum[RPB][8], s_sq[RPB][8];
    __shared__ float  s_b1[64], s_W2[256], s_b2[4];
    __shared__ float4 s_cmb[RPB];          // per-row combined features
    __shared__ float  s_red[24];           // 8 warps x {tsum, tot, p2}

    const int t    = threadIdx.x;
    const int lane = t & 31;
    const int wid  = t >> 5;
    const int b    = blockIdx.x;
    const int q    = t >> 6;   // encoder / W1-quarter index
    const int k    = t & 63;   // column within 64

    // stage head weights (consumed after many barriers — no sync needed here)
    if (t < 64) s_b1[t] = b1[t];
    s_W2[t] = W2[t];
    if (t < 4) s_b2[t] = b2[t];

    // ======================= feat phase: 4 rows =======================
    for (int j = 0; j < RPB; j++) {
        const float* row = prices + (size_t)(b * RPB + j) * S_;

        // own chunk: 16 contiguous floats
        float p[CHUNK];
        {
            const float4* r4 = reinterpret_cast<const float4*>(row) + t * (CHUNK / 4);
#pragma unroll
            for (int qq = 0; qq < 4; qq++) {
                float4 v = r4[qq];
                p[qq * 4 + 0] = v.x; p[qq * 4 + 1] = v.y;
                p[qq * 4 + 2] = v.z; p[qq * 4 + 3] = v.w;
            }
        }

        // 20-float halo ending just before own chunk ((t*16-20)*4B is 16B aligned)
        float h[20];
        if (t >= 2) {
            const float4* r4 = reinterpret_cast<const float4*>(row + t * CHUNK - 20);
#pragma unroll
            for (int qq = 0; qq < 5; qq++) {
                float4 v = r4[qq];
                h[qq * 4 + 0] = v.x; h[qq * 4 + 1] = v.y;
                h[qq * 4 + 2] = v.z; h[qq * 4 + 3] = v.w;
            }
        } else if (t == 1) {
#pragma unroll
            for (int jj = 0; jj < 4; jj++) h[jj] = 0.f;
            const float4* r4 = reinterpret_cast<const float4*>(row);
#pragma unroll
            for (int qq = 0; qq < 4; qq++) {
                float4 v = r4[qq];
                h[4 + qq * 4 + 0] = v.x; h[4 + qq * 4 + 1] = v.y;
                h[4 + qq * 4 + 2] = v.z; h[4 + qq * 4 + 3] = v.w;
            }
        } else {
#pragma unroll
            for (int jj = 0; jj < 20; jj++) h[jj] = 0.f;
        }

        float W = 0.f;
#pragma unroll
        for (int jj = 0; jj < 20; jj++) W += h[jj];   // window ending at i0-1

        float tsum = 0.f, tot = 0.f, p2 = 0.f;
        if (t >= 2) {
#pragma unroll
            for (int kk = 0; kk < CHUNK; kk++) {
                W += p[kk] - h[kk];
                float sma = W * 0.05f;
                tsum += __fdividef(p[kk] - sma, sma + EPS_);
                tot += p[kk];
                p2   = fmaf(p[kk], p[kk], p2);
            }
        } else {
            // t==0/1: clamped start; zero-filled halo makes W correct
#pragma unroll
            for (int kk = 0; kk < CHUNK; kk++) {
                int i = t * CHUNK + kk;
                W += p[kk] - h[kk];
                float cnt = fminf((float)(i + 1), 20.f);
                float sma = __fdividef(W, cnt);
                tsum += __fdividef(p[kk] - sma, sma + EPS_);
                tot += p[kk];
                p2   = fmaf(p[kk], p[kk], p2);
            }
        }

        // block reduce {tsum, tot, p2}
#pragma unroll
        for (int off = 16; off > 0; off >>= 1) {
            tsum += __shfl_xor_sync(0xffffffffu, tsum, off);
            tot  += __shfl_xor_sync(0xffffffffu, tot,  off);
            p2   += __shfl_xor_sync(0xffffffffu, p2,   off);
        }
        if (lane == 0) {
            s_red[wid]      = tsum;
            s_red[8 + wid]  = tot;
            s_red[16 + wid] = p2;
        }
        __syncthreads();

        if (t == TPB - 1) {   // t=255 holds p_last=p[15] (i=4095), p_m10=p[6] (i=4086)
            float T = 0.f, PS = 0.f, P2 = 0.f;
#pragma unroll
            for (int i = 0; i < 8; i++) {
                T  += s_red[i];
                PS += s_red[8 + i];
                P2 += s_red[16 + i];
            }
            float mean    = PS * (1.0f / S_);
            float f_trend = T * (1.0f / S_);
            float pl = p[CHUNK - 1], pm10 = p[CHUNK - 10];
            float f_mom = (pl - pm10) / (pm10 + EPS_);
            float f_mr  = (pl - mean) / (mean + EPS_);
            float var   = (P2 - (float)S_ * mean * mean) * (1.0f / (float)(S_ - 1));
            float f_cyc = sqrtf(fmaxf(var, 0.f)) / (mean + EPS_);
            s_cmb[j] = make_float4(f_trend, f_mom, f_mr, f_cyc);
        }
        __syncthreads();      // s_red free for next row; s_cmb visible to all
    }

    // ======================= mlp phase (v2, RPB=4) =======================
    // head_w1 quarter-slice in registers (feat registers are dead by now)
    float w[64];
#pragma unroll
    for (int jj = 0; jj < 64; jj++) w[jj] = W1[(q * 64 + jj) * 64 + k];

    const float ew0 = enc_w[q * 256 + 0 * 64 + k];
    const float ew1 = enc_w[q * 256 + 1 * 64 + k];
    const float ew2 = enc_w[q * 256 + 2 * 64 + k];
    const float ew3 = enc_w[q * 256 + 3 * 64 + k];
    const float eb  = enc_b[q * 64 + k];
    const float gg  = enc_g[q * 64 + k];
    const float bb  = enc_beta[q * 64 + k];

    // phase 1: encoder + relu
    float x[RPB];
#pragma unroll
    for (int r = 0; r < RPB; r++) {
        float4 cb = s_cmb[r];
        float pre = eb;
        pre = fmaf(ew0, cb.x, pre);
        pre = fmaf(ew1, cb.y, pre);
        pre = fmaf(ew2, cb.z, pre);
        pre = fmaf(ew3, cb.w, pre);
        x[r] = fmaxf(pre, 0.f);
    }

    // phase 2: LN reductions
#pragma unroll
    for (int r = 0; r < RPB; r++) {
        float s = x[r], s2 = x[r] * x[r];
#pragma unroll
        for (int off = 16; off > 0; off >>= 1) {
            s  += __shfl_xor_sync(0xffffffffu, s,  off);
            s2 += __shfl_xor_sync(0xffffffffu, s2, off);
        }
        if (lane == 0) { s_sum[r][wid] = s; s_sq[r][wid] = s2; }
    }
    __syncthreads();

    const int gw = q * 2;
#pragma unroll
    for (int r = 0; r < RPB; r++) {
        float gs   = s_sum[r][gw] + s_sum[r][gw + 1];
        float gs2  = s_sq[r][gw]  + s_sq[r][gw + 1];
        float mu   = gs * (1.f / 64.f);
        float varr = gs2 * (1.f / 64.f) - mu * mu;
        float y = (x[r] - mu) * rsqrtf(varr + LNEPS_) * gg + bb;
        s_rf[r][t] = y;
        rf_out[(size_t)(b * RPB + r) * 256 + t] = y;   // coalesced
    }
    __syncthreads();

    // phase 3: GEMM1 quarter partials
#pragma unroll
    for (int r = 0; r < RPB; r++) {
        const float4* rf4 = reinterpret_cast<const float4*>(&s_rf[r][q * 64]);
        float a0 = 0.f, a1 = 0.f, a2 = 0.f, a3 = 0.f;
#pragma unroll
        for (int jj = 0; jj < 16; jj++) {
            float4 rv = rf4[jj];            // warp-broadcast (conflict-free)
            a0 = fmaf(w[jj * 4 + 0], rv.x, a0);
            a1 = fmaf(w[jj * 4 + 1], rv.y, a1);
            a2 = fmaf(w[jj * 4 + 2], rv.z, a2);
            a3 = fmaf(w[jj * 4 + 3], rv.w, a3);
        }
        s_part[r][t] = (a0 + a1) + (a2 + a3);
    }
    __syncthreads();

    // phase 4: combine quarters, bias, relu (RPB*64 == TPB: one pass)
    {
        int r  = t >> 6;
        int kk = t & 63;
        float hh = s_b1[kk] + s_part[r][kk] + s_part[r][64 + kk]
                            + s_part[r][128 + kk] + s_part[r][192 + kk];
        s_h[r][kk] = fmaxf(hh, 0.f);
    }
    __syncthreads();

    // phase 5: logits + softmax — warp 0 entire (legal full-mask shuffles),
    // lanes 16-31 compute duplicates, only lanes 0-15 write.
    if (t < 32) {
        int r = (t >> 2) & 3;
        int c = t & 3;
        float l = s_b2[c];
#pragma unroll
        for (int kk = 0; kk < 64; kk++)
            l = fmaf(s_h[r][kk], s_W2[kk * 4 + c], l);

        float m = l;
        m = fmaxf(m, __shfl_xor_sync(0xffffffffu, m, 1));
        m = fmaxf(m, __shfl_xor_sync(0xffffffffu, m, 2));
        float e = __expf(l - m);
        float den = e;
        den += __shfl_xor_sync(0xffffffffu, den, 1);
        den += __shfl_xor_sync(0xffffffffu, den, 2);
        if (t < 16)
            probs_out[(size_t)(b * RPB + r) * 4 + c] = __fdividef(e, den);
    }
}

// ---------------------------------------------------------------------------
extern "C" void kernel_launch(void* const* d_in, const int* in_sizes, int n_in,
                              void* d_out, int out_size)
{
    const float* prices   = (const float*)d_in[0];  // (8192, 4096, 1)
    const float* enc_w    = (const float*)d_in[1];  // (4, 4, 64)
    const float* enc_b    = (const float*)d_in[2];  // (4, 64)
    const float* enc_g    = (const float*)d_in[3];  // (4, 64)
    const float* enc_beta = (const float*)d_in[4];  // (4, 64)
    const float* head_w1  = (const float*)d_in[5];  // (256, 64)
    const float* head_b1  = (const float*)d_in[6];  // (64,)
    const float* head_w2  = (const float*)d_in[7];  // (64, 4)
    const float* head_b2  = (const float*)d_in[8];  // (4,)

    float* out       = (float*)d_out;
    float* rf_out    = out;                      // 8192*256
    float* probs_out = out + (size_t)B_ * 256;   // 8192*4

    fused_kernel<<<GRID_, TPB>>>(prices, enc_w, enc_b, enc_g, enc_beta,
                                 head_w1, head_b1, head_w2, head_b2,
                                 rf_out, probs_out);
}

// round 17
// speedup vs baseline: 1.3313x; 1.3313x over previous
#include <cuda_runtime.h>
#include <cstdint>

#define B_ 8192
#define S_ 4096
#define TPB 256
#define CHUNK 16           // S_ / TPB
#define EPS_ 1e-8f
#define LNEPS_ 1e-5f

// scratch for per-row features (B_ x 4) — __device__ global, no allocation
__device__ float g_combined[B_ * 4];

__device__ __forceinline__ int padi(int i) { return i + (i >> 4); }  // stride-17, conflict-free

// ---------------------------------------------------------------------------
// Kernel A (v1, best measured 34.5-39us): smem prefix scan + lag-20 gather.
// ---------------------------------------------------------------------------
__global__ void __launch_bounds__(TPB) feat_kernel(const float* __restrict__ prices)
{
    __shared__ float sI[S_ + (S_ >> 4)];   // padded inclusive prefix sums
    __shared__ float s_scan[16];
    __shared__ float s_red[16];
    __shared__ float s_plast, s_pm10;

    const int b    = blockIdx.x;
    const int t    = threadIdx.x;
    const int lane = t & 31;
    const int wid  = t >> 5;

    const float4* row4 =
        reinterpret_cast<const float4*>(prices + (size_t)b * S_) + t * (CHUNK / 4);

    float p[CHUNK];
#pragma unroll
    for (int q = 0; q < CHUNK / 4; q++) {
        float4 v = row4[q];
        p[q * 4 + 0] = v.x; p[q * 4 + 1] = v.y;
        p[q * 4 + 2] = v.z; p[q * 4 + 3] = v.w;
    }

    // local inclusive scan + sum of squares
    float c[CHUNK];
    float p2 = p[0] * p[0];
    c[0] = p[0];
#pragma unroll
    for (int k = 1; k < CHUNK; k++) {
        c[k] = c[k - 1] + p[k];
        p2   = fmaf(p[k], p[k], p2);
    }
    const float tot = c[CHUNK - 1];

    // block-wide exclusive scan of per-thread totals
    float v = tot;
#pragma unroll
    for (int off = 1; off < 32; off <<= 1) {
        float n = __shfl_up_sync(0xffffffffu, v, off);
        if (lane >= off) v += n;
    }
    if (lane == 31) s_scan[wid] = v;
    if (t == TPB - 1) { s_plast = p[CHUNK - 1]; s_pm10 = p[CHUNK - 10]; } // i=4095, i=4086
    __syncthreads();
    if (wid == 0) {
        float w = (lane < 8) ? s_scan[lane] : 0.f;
#pragma unroll
        for (int off = 1; off < 8; off <<= 1) {
            float n = __shfl_up_sync(0xffffffffu, w, off);
            if (lane >= off) w += n;
        }
        if (lane < 8) s_scan[8 + lane] = w;
    }
    __syncthreads();
    const float base = ((wid > 0) ? s_scan[8 + wid - 1] : 0.f) + (v - tot);

#pragma unroll
    for (int k = 0; k < CHUNK; k++) sI[padi(t * CHUNK + k)] = base + c[k];
    __syncthreads();

    // trend: (p - sma20)/(sma20 + eps); sma20 = (I[i]-I[i-20]) / min(i+1,20)
    float tsum = 0.f;
    if (t >= 2) {
#pragma unroll
        for (int k = 0; k < CHUNK; k++) {
            int   i  = t * CHUNK + k;
            float I  = base + c[k];
            float Ip = sI[padi(i - 20)];
            float sma = (I - Ip) * 0.05f;
            tsum += __fdividef(p[k] - sma, sma + EPS_);
        }
    } else {
#pragma unroll
        for (int k = 0; k < CHUNK; k++) {
            int   i  = t * CHUNK + k;
            float I  = base + c[k];
            float Ip = (i >= 20) ? sI[padi(i - 20)] : 0.f;
            float cnt = (i >= 20) ? 20.f : (float)(i + 1);
            float sma = __fdividef(I - Ip, cnt);
            tsum += __fdividef(p[k] - sma, sma + EPS_);
        }
    }

#pragma unroll
    for (int off = 16; off > 0; off >>= 1) {
        tsum += __shfl_xor_sync(0xffffffffu, tsum, off);
        p2   += __shfl_xor_sync(0xffffffffu, p2,   off);
    }
    if (lane == 0) { s_red[wid] = tsum; s_red[8 + wid] = p2; }
    __syncthreads();

    if (t == 0) {
        float T = 0.f, P2 = 0.f;
#pragma unroll
        for (int i = 0; i < 8; i++) { T += s_red[i]; P2 += s_red[8 + i]; }
        float psum  = sI[padi(S_ - 1)];
        float mean  = psum * (1.0f / S_);
        float f_trend = T * (1.0f / S_);
        float pl = s_plast, pm10 = s_pm10;
        float f_mom = (pl - pm10) / (pm10 + EPS_);
        float f_mr  = (pl - mean) / (mean + EPS_);
        float var   = (P2 - (float)S_ * mean * mean) * (1.0f / (float)(S_ - 1));
        float f_cyc = sqrtf(fmaxf(var, 0.f)) / (mean + EPS_);
        *reinterpret_cast<float4*>(&g_combined[b * 4]) =
            make_float4(f_trend, f_mom, f_mr, f_cyc);
    }
}

// ---------------------------------------------------------------------------
// Kernel B (v4): v2 structure + f32x2 packed FMA in GEMM1 (FFMA2).
// ---------------------------------------------------------------------------
#define RPB 16                      // rows per block
#define MLP_GRID (B_ / RPB)         // 512

__global__ void __launch_bounds__(TPB) mlp_kernel(
    const float* __restrict__ enc_w,  const float* __restrict__ enc_b,
    const float* __restrict__ enc_g,  const float* __restrict__ enc_beta,
    const float* __restrict__ W1,     const float* __restrict__ b1,
    const float* __restrict__ W2,     const float* __restrict__ b2,
    float* __restrict__ rf_out, float* __restrict__ probs_out)
{
    __shared__ float s_cmb[RPB * 4];           // combined features for tile
    __shared__ float s_rf[RPB][256];           // layernormed features
    __shared__ float s_part[RPB][256];         // GEMM1 partials (per quarter)
    __shared__ float s_h[RPB][65];             // hidden (padded: stride 65)
    __shared__ float s_sum[RPB][8];            // LN partial sums per (row, warp)
    __shared__ float s_sq[RPB][8];
    __shared__ float s_b1[64], s_W2[256], s_b2[4];

    const int t    = threadIdx.x;
    const int lane = t & 31, wid = t >> 5;
    const int q = t >> 6;   // encoder index / quarter of head_w1 rows
    const int k = t & 63;   // column within 64
    const int r0 = blockIdx.x * RPB;

    // head_w1 quarter-slice, packed into f32x2 pairs:
    // w2[2*jj]   = {W1[4jj][k],   W1[4jj+1][k]}
    // w2[2*jj+1] = {W1[4jj+2][k], W1[4jj+3][k]}   (rows offset by q*64)
    unsigned long long w2[32];
#pragma unroll
    for (int jj = 0; jj < 16; jj++) {
        float a = W1[(q * 64 + jj * 4 + 0) * 64 + k];
        float bq = W1[(q * 64 + jj * 4 + 1) * 64 + k];
        float cq = W1[(q * 64 + jj * 4 + 2) * 64 + k];
        float dq = W1[(q * 64 + jj * 4 + 3) * 64 + k];
        asm("mov.b64 %0, {%1, %2};" : "=l"(w2[jj * 2 + 0])
            : "r"(__float_as_uint(a)), "r"(__float_as_uint(bq)));
        asm("mov.b64 %0, {%1, %2};" : "=l"(w2[jj * 2 + 1])
            : "r"(__float_as_uint(cq)), "r"(__float_as_uint(dq)));
    }

    const float ew0 = enc_w[q * 256 + 0 * 64 + k];
    const float ew1 = enc_w[q * 256 + 1 * 64 + k];
    const float ew2 = enc_w[q * 256 + 2 * 64 + k];
    const float ew3 = enc_w[q * 256 + 3 * 64 + k];
    const float eb  = enc_b[q * 64 + k];
    const float gg  = enc_g[q * 64 + k];
    const float bb  = enc_beta[q * 64 + k];

    if (t < 64) s_b1[t] = b1[t];
    s_W2[t] = W2[t];
    if (t < 4) s_b2[t] = b2[t];
    if (t < RPB * 4) s_cmb[t] = g_combined[r0 * 4 + t];
    __syncthreads();

    // ---- phase 1: encoder pre-activation + relu for all 16 rows ----
    float x[RPB];
#pragma unroll
    for (int r = 0; r < RPB; r++) {
        float pre = eb;
        pre = fmaf(ew0, s_cmb[r * 4 + 0], pre);
        pre = fmaf(ew1, s_cmb[r * 4 + 1], pre);
        pre = fmaf(ew2, s_cmb[r * 4 + 2], pre);
        pre = fmaf(ew3, s_cmb[r * 4 + 3], pre);
        x[r] = fmaxf(pre, 0.f);
    }

    // ---- phase 2: LN reductions (warp shuffles, all rows) ----
#pragma unroll
    for (int r = 0; r < RPB; r++) {
        float s = x[r], s2 = x[r] * x[r];
#pragma unroll
        for (int off = 16; off > 0; off >>= 1) {
            s  += __shfl_xor_sync(0xffffffffu, s,  off);
            s2 += __shfl_xor_sync(0xffffffffu, s2, off);
        }
        if (lane == 0) { s_sum[r][wid] = s; s_sq[r][wid] = s2; }
    }
    __syncthreads();

    const int gw = q * 2;
#pragma unroll
    for (int r = 0; r < RPB; r++) {
        float gs   = s_sum[r][gw] + s_sum[r][gw + 1];
        float gs2  = s_sq[r][gw]  + s_sq[r][gw + 1];
        float mu   = gs * (1.f / 64.f);
        float varr = gs2 * (1.f / 64.f) - mu * mu;
        float y = (x[r] - mu) * rsqrtf(varr + LNEPS_) * gg + bb;
        s_rf[r][t] = y;
        rf_out[(size_t)(r0 + r) * 256 + t] = y;   // coalesced per row
    }
    __syncthreads();

    // ---- phase 3: GEMM1 partials — packed f32x2 FMA (FFMA2), 2 chains ----
#pragma unroll
    for (int r = 0; r < RPB; r++) {
        const ulonglong2* rf2 = reinterpret_cast<const ulonglong2*>(&s_rf[r][q * 64]);
        unsigned long long accA = 0ull, accB = 0ull;   // {0,0} bit pattern
#pragma unroll
        for (int jj = 0; jj < 16; jj++) {
            ulonglong2 rv = rf2[jj];   // LDS.128 broadcast (same addr warp-wide)
            asm("fma.rn.f32x2 %0, %1, %2, %0;"
                : "+l"(accA) : "l"(w2[jj * 2 + 0]), "l"(rv.x));
            asm("fma.rn.f32x2 %0, %1, %2, %0;"
                : "+l"(accB) : "l"(w2[jj * 2 + 1]), "l"(rv.y));
        }
        unsigned long long accS;
        asm("add.rn.f32x2 %0, %1, %2;" : "=l"(accS) : "l"(accA), "l"(accB));
        uint32_t lo, hi;
        asm("mov.b64 {%0, %1}, %2;" : "=r"(lo), "=r"(hi) : "l"(accS));
        s_part[r][t] = __uint_as_float(lo) + __uint_as_float(hi);
    }
    __syncthreads();

    // ---- phase 4: combine quarters, bias, relu -> s_h ----
#pragma unroll
    for (int i = 0; i < RPB * 64 / TPB; i++) {       // 4 iterations
        int idx = t + i * TPB;
        int r   = idx >> 6;
        int kk  = idx & 63;
        float hh = s_b1[kk] + s_part[r][kk] + s_part[r][64 + kk]
                            + s_part[r][128 + kk] + s_part[r][192 + kk];
        s_h[r][kk] = fmaxf(hh, 0.f);
    }
    __syncthreads();

    // ---- phase 5: logits + softmax (64 threads: one per (row, class)) ----
    if (t < RPB * 4) {
        int r = t >> 2, c = t & 3;
        float l = s_b2[c];
#pragma unroll
        for (int kk = 0; kk < 64; kk++)
            l = fmaf(s_h[r][kk], s_W2[kk * 4 + c], l);   // stride-65 rows: conflict-free

        float m = l;
        m = fmaxf(m, __shfl_xor_sync(0xffffffffu, m, 1));
        m = fmaxf(m, __shfl_xor_sync(0xffffffffu, m, 2));
        float e = __expf(l - m);
        float den = e;
        den += __shfl_xor_sync(0xffffffffu, den, 1);
        den += __shfl_xor_sync(0xffffffffu, den, 2);
        probs_out[(size_t)(r0 + r) * 4 + c] = __fdividef(e, den);
    }
}

// ---------------------------------------------------------------------------
extern "C" void kernel_launch(void* const* d_in, const int* in_sizes, int n_in,
                              void* d_out, int out_size)
{
    const float* prices   = (const float*)d_in[0];  // (8192, 4096, 1)
    const float* enc_w    = (const float*)d_in[1];  // (4, 4, 64)
    const float* enc_b    = (const float*)d_in[2];  // (4, 64)
    const float* enc_g    = (const float*)d_in[3];  // (4, 64)
    const float* enc_beta = (const float*)d_in[4];  // (4, 64)
    const float* head_w1  = (const float*)d_in[5];  // (256, 64)
    const float* head_b1  = (const float*)d_in[6];  // (64,)
    const float* head_w2  = (const float*)d_in[7];  // (64, 4)
    const float* head_b2  = (const float*)d_in[8];  // (4,)

    float* out       = (float*)d_out;
    float* rf_out    = out;                      // 8192*256
    float* probs_out = out + (size_t)B_ * 256;   // 8192*4

    feat_kernel<<<B_, TPB>>>(prices);
    mlp_kernel<<<MLP_GRID, TPB>>>(enc_w, enc_b, enc_g, enc_beta,
                                  head_w1, head_b1, head_w2, head_b2,
                                  rf_out, probs_out);
}